// round 8
// baseline (speedup 1.0000x reference)
#include <cuda_runtime.h>
#include <cstdint>

#define D_MODEL 512
#define KEY_DIM 128
#define BS_N 16
#define CTX_PER 1024
#define ARGS_PER 32
#define N_ARGS (BS_N * ARGS_PER)      /* 512  */
#define N_CTX  (BS_N * CTX_PER)       /* 16384 */
#define P_TOT  (N_ARGS * CTX_PER)     /* 524288 */

// Scratch (allocation-free rule: device globals). Accessed ONLY from device
// code -- host-side references give the host shadow symbol (R3 bug).
__device__ float g_Qp[N_ARGS * D_MODEL];   // Qp[r,d] = sum_k arg[r,k] * W[d,k]
__device__ float g_qb[N_ARGS];             // qb[r]   = arg[r,:] . b

// ---------------------------------------------------------------------------
__device__ __forceinline__ uint32_t f2tf32(float f) {
    uint32_t r;
    asm("cvt.rna.tf32.f32 %0, %1;" : "=r"(r) : "f"(f));
    return r;
}

// D(16x8) += A(16x8,row) * B(8x8,col)   tf32 inputs, fp32 accum
__device__ __forceinline__ void mma_tf32(float (&d)[4], const uint32_t (&a)[4],
                                         uint32_t b0, uint32_t b1) {
    asm volatile(
        "mma.sync.aligned.m16n8k8.row.col.f32.tf32.tf32.f32 "
        "{%0,%1,%2,%3}, {%4,%5,%6,%7}, {%8,%9}, {%0,%1,%2,%3};"
        : "+f"(d[0]), "+f"(d[1]), "+f"(d[2]), "+f"(d[3])
        : "r"(a[0]), "r"(a[1]), "r"(a[2]), "r"(a[3]), "r"(b0), "r"(b1));
}

// ldmatrix x4 (b16 view of 32-bit data): 4 tiles of 8 rows x 16B; for tf32
// each tile is 8x4 and thread t gets element [t/4][t%4] == (qr,qc).
__device__ __forceinline__ void ldsm_x4(uint32_t (&r)[4], uint32_t addr) {
    asm volatile(
        "ldmatrix.sync.aligned.m8n8.x4.shared.b16 {%0,%1,%2,%3}, [%4];"
        : "=r"(r[0]), "=r"(r[1]), "=r"(r[2]), "=r"(r[3]) : "r"(addr));
}

__device__ __forceinline__ uint32_t s2u(const void* p) {
    return (uint32_t)__cvta_generic_to_shared(p);
}

// ---------------------------------------------------------------------------
// Tensor-core GEMM: D[32 x 64] tile of Qrows[32,KD] @ Crows[64,KD]^T
//   256 threads = 8 warps as 2(m) x 4(n): warp owns 16 rows x 16 cols.
//   K chunked by 64, double-buffered smem (exactly 48KB -> 2 CTAs/SM).
//   Smem rows are 64 tf32 with XOR swizzle (16B segment ^ (row&7)) ->
//   conflict-free LDSM; tf32 pre-converted at store.
// LOGITS: Q = g_Qp, adds g_qb, writes logits + rows planes (stride 1024).
// !LOGITS (qp): Q = arg_values, C = W, writes g_Qp (stride 512);
//               blockIdx.x==0 also computes g_qb (quad-shuffle reduction).
// ---------------------------------------------------------------------------
template<int KD, bool LOGITS>
__global__ __launch_bounds__(256, 2) void gemm_tc(const float* __restrict__ Qm,
                                                  const float* __restrict__ Cm,
                                                  const float* __restrict__ bv,
                                                  float* __restrict__ out,
                                                  float* __restrict__ rows_out) {
    constexpr int NCH  = KD / 64;                   // K chunks
    constexpr int OSTR = LOGITS ? CTX_PER : D_MODEL;

    __shared__ uint32_t Qs[2][32 * 64];             // 16 KB
    __shared__ uint32_t Cs[2][64 * 64];             // 32 KB

    const int tid  = threadIdx.x;
    const int lane = tid & 31;
    const int warp = tid >> 5;
    const int wm   = warp >> 2;          // 0..1  (row half)
    const int wn   = warp & 3;           // 0..3  (col quarter)
    const int qr   = lane >> 2;          // fragment groupID  (0..7)
    const int qc   = lane & 3;           // fragment threadID (0..3)

    const float* Qbase = LOGITS ? (const float*)g_Qp : Qm;
    const int qrow_base = blockIdx.y * 32;
    const int crow_base = (LOGITS ? blockIdx.y * CTX_PER : 0) + blockIdx.x * 64;
    const int ocol_base = blockIdx.x * 64;

    // ---- loader indices (16B segment = 4 floats; swizzle: seg ^ (row & 7))
    const int lq_row = tid >> 3;                 // 0..31
    const int lq_seg = (tid & 7) * 2;            // segments {0,2,..,14}
    const float* qsrc = Qbase + (size_t)(qrow_base + lq_row) * KD + lq_seg * 4;

    const int lc_row = tid >> 2;                 // 0..63
    const int lc_seg = (tid & 3) * 4;            // segments {0,4,8,12}
    const float* csrc = Cm + (size_t)(crow_base + lc_row) * KD + lc_seg * 4;

    // ---- LDSM lane addresses
    // A: rows 16*wm + (lane&15); hi = lane>>4 selects k segment pair member.
    const int arow = 16 * wm + (lane & 15);
    const int ahi  = lane >> 4;                  // 0/1
    const int amask = arow & 7;
    const uint32_t abase[2] = { s2u(&Qs[0][arow * 64]), s2u(&Qs[1][arow * 64]) };
    // B: rows (cols) 16*wn + (lane&15)
    const int brow = 16 * wn + (lane & 15);
    const int bhi  = lane >> 4;
    const int bmask = brow & 7;
    const uint32_t bbase[2] = { s2u(&Cs[0][brow * 64]), s2u(&Cs[1][brow * 64]) };

    float acc[2][4] = {};                        // [n-tile][frag]

    // ---- prologue: chunk 0 -> buffer 0
    {
        #pragma unroll
        for (int jj = 0; jj < 2; jj++) {
            float4 q = *(const float4*)(qsrc + jj * 4);
            int sw = (lq_seg + jj) ^ (lq_row & 7);
            *(uint4*)&Qs[0][lq_row * 64 + sw * 4] =
                make_uint4(f2tf32(q.x), f2tf32(q.y), f2tf32(q.z), f2tf32(q.w));
        }
        #pragma unroll
        for (int jj = 0; jj < 4; jj++) {
            float4 c = *(const float4*)(csrc + jj * 4);
            int sw = (lc_seg + jj) ^ (lc_row & 7);
            *(uint4*)&Cs[0][lc_row * 64 + sw * 4] =
                make_uint4(f2tf32(c.x), f2tf32(c.y), f2tf32(c.z), f2tf32(c.w));
        }
    }
    __syncthreads();

    #pragma unroll 1
    for (int it = 0; it < NCH; it++) {
        const int buf = it & 1;

        // prefetch next chunk to registers (long gap before STS)
        float4 qn[2], cn[4];
        if (it + 1 < NCH) {
            #pragma unroll
            for (int jj = 0; jj < 2; jj++)
                qn[jj] = *(const float4*)(qsrc + (it + 1) * 64 + jj * 4);
            #pragma unroll
            for (int jj = 0; jj < 4; jj++)
                cn[jj] = *(const float4*)(csrc + (it + 1) * 64 + jj * 4);
        }

        // compute current chunk: 8 k8 steps, 1 A-LDSM + 1 B-LDSM + 2 MMA each
        #pragma unroll
        for (int kk = 0; kk < 8; kk++) {
            uint32_t a[4], b[4];
            const int sa = (kk * 2 + ahi) ^ amask;
            const int sb = (kk * 2 + bhi) ^ bmask;
            ldsm_x4(a, abase[buf] + sa * 16);
            ldsm_x4(b, bbase[buf] + sb * 16);
            mma_tf32(acc[0], a, b[0], b[2]);     // cols 16wn+0..7
            mma_tf32(acc[1], a, b[1], b[3]);     // cols 16wn+8..15
        }

        // store next chunk into other buffer
        if (it + 1 < NCH) {
            const int nb = buf ^ 1;
            #pragma unroll
            for (int jj = 0; jj < 2; jj++) {
                int sw = (lq_seg + jj) ^ (lq_row & 7);
                *(uint4*)&Qs[nb][lq_row * 64 + sw * 4] =
                    make_uint4(f2tf32(qn[jj].x), f2tf32(qn[jj].y),
                               f2tf32(qn[jj].z), f2tf32(qn[jj].w));
            }
            #pragma unroll
            for (int jj = 0; jj < 4; jj++) {
                int sw = (lc_seg + jj) ^ (lc_row & 7);
                *(uint4*)&Cs[nb][lc_row * 64 + sw * 4] =
                    make_uint4(f2tf32(cn[jj].x), f2tf32(cn[jj].y),
                               f2tf32(cn[jj].z), f2tf32(cn[jj].w));
            }
            __syncthreads();
        }
    }

    // ---- epilogue: warp tile rows [16wm,16wm+16), cols [16wn,16wn+16)
    #pragma unroll
    for (int nt = 0; nt < 2; nt++) {
        #pragma unroll
        for (int half = 0; half < 2; half++) {
            const int rg = qrow_base + 16 * wm + qr + half * 8;   // global row
            const int col = ocol_base + 16 * wn + nt * 8 + qc * 2;
            const size_t off = (size_t)rg * OSTR + col;
            float v0 = acc[nt][half * 2 + 0];
            float v1 = acc[nt][half * 2 + 1];
            if (LOGITS) {
                const float qb = g_qb[rg];
                *(float2*)(out + off) = make_float2(v0 + qb, v1 + qb);
                if (rows_out) {
                    float fr = (float)rg;
                    *(float2*)(rows_out + off) = make_float2(fr, fr);
                }
            } else {
                *(float2*)(g_Qp + off) = make_float2(v0, v1);
            }
        }
    }

    // ---- fused qb (qp kernel only, one column of blocks)
    if (!LOGITS && blockIdx.x == 0 && tid < 128) {
        const int row = qrow_base + (tid >> 2);
        const int seg = tid & 3;
        const float* ap = Qm + (size_t)row * KEY_DIM + seg * 32;
        const float* bp = bv + seg * 32;
        float s = 0.f;
        #pragma unroll
        for (int k = 0; k < 8; k++) {
            float4 a  = *(const float4*)(ap + 4 * k);
            float4 bb = *(const float4*)(bp + 4 * k);
            s = fmaf(a.x, bb.x, s); s = fmaf(a.y, bb.y, s);
            s = fmaf(a.z, bb.z, s); s = fmaf(a.w, bb.w, s);
        }
        s += __shfl_xor_sync(0xffffffffu, s, 1);
        s += __shfl_xor_sync(0xffffffffu, s, 2);
        if (seg == 0) g_qb[row] = s;
    }
}

// ---------------------------------------------------------------------------
extern "C" void kernel_launch(void* const* d_in, const int* in_sizes, int n_in,
                              void* d_out, int out_size) {
    // Identify inputs by element count (arg_values and W share 65536 ->
    // disambiguated by order: arg_values precedes W in the input dict).
    const float* argv = nullptr;
    const float* ctxv = nullptr;
    const float* Wm   = nullptr;
    const float* bv   = nullptr;
    int seen_65536 = 0;
    for (int i = 0; i < n_in; i++) {
        long sz = in_sizes[i];
        if (sz == (long)N_CTX * D_MODEL) {
            ctxv = (const float*)d_in[i];
        } else if (sz == (long)N_ARGS * KEY_DIM) {   // == D_MODEL*KEY_DIM too
            if (seen_65536++ == 0) argv = (const float*)d_in[i];
            else                   Wm   = (const float*)d_in[i];
        } else if (sz == KEY_DIM) {
            bv = (const float*)d_in[i];
        }
    }

    float* out        = (float*)d_out;
    float* rows_out   = nullptr;
    float* logits_out = out;
    if (out_size >= 2 * P_TOT) {        // (rows, logits) concatenated
        rows_out   = out;
        logits_out = out + P_TOT;
    }

    // Qp = arg @ W^T (+ fused qb): M=512 rows (16 y-tiles of 32),
    // N=512 dims (8 x-tiles of 64), K=128 (2 chunks)
    gemm_tc<KEY_DIM, false><<<dim3(8, 16), 256>>>(argv, Wm, bv, nullptr, nullptr);

    // logits: per state (blockIdx.y): [32,1024] = Qp_s @ C_s^T + qb,
    // 16 x-tiles of 64 cols, K=512 (8 chunks) -> 256 CTAs, 2 CTAs/SM
    gemm_tc<D_MODEL, true><<<dim3(16, 16), 256>>>(nullptr, ctxv, nullptr,
                                                  logits_out, rows_out);
}

// round 9
// speedup vs baseline: 1.2204x; 1.2204x over previous
#include <cuda_runtime.h>
#include <cstdint>

#define D_MODEL 512
#define KEY_DIM 128
#define BS_N 16
#define CTX_PER 1024
#define ARGS_PER 32
#define N_ARGS (BS_N * ARGS_PER)      /* 512  */
#define N_CTX  (BS_N * CTX_PER)       /* 16384 */
#define P_TOT  (N_ARGS * CTX_PER)     /* 524288 */

// Scratch (allocation-free rule: device globals). Accessed ONLY from device
// code -- host-side references give the host shadow symbol (R3 bug).
__device__ float g_Qp[N_ARGS * D_MODEL];   // Qp[r,d] = sum_k arg[r,k] * W[d,k]
__device__ float g_qb[N_ARGS];             // qb[r]   = arg[r,:] . b

// ---------------------------------------------------------------------------
__device__ __forceinline__ uint32_t f2tf32(float f) {
    uint32_t r;
    asm("cvt.rna.tf32.f32 %0, %1;" : "=r"(r) : "f"(f));
    return r;
}
__device__ __forceinline__ uint32_t bits2tf32(uint32_t b) {
    return f2tf32(__uint_as_float(b));
}

// D(16x8) += A(16x8,row) * B(8x8,col)   tf32 inputs, fp32 accum
__device__ __forceinline__ void mma_tf32(float (&d)[4], const uint32_t (&a)[4],
                                         uint32_t b0, uint32_t b1) {
    asm volatile(
        "mma.sync.aligned.m16n8k8.row.col.f32.tf32.tf32.f32 "
        "{%0,%1,%2,%3}, {%4,%5,%6,%7}, {%8,%9}, {%0,%1,%2,%3};"
        : "+f"(d[0]), "+f"(d[1]), "+f"(d[2]), "+f"(d[3])
        : "r"(a[0]), "r"(a[1]), "r"(a[2]), "r"(a[3]), "r"(b0), "r"(b1));
}

// ldmatrix x4 (b16 view of 32-bit data): verified on HW in R7/R8.
__device__ __forceinline__ void ldsm_x4(uint32_t (&r)[4], uint32_t addr) {
    asm volatile(
        "ldmatrix.sync.aligned.m8n8.x4.shared.b16 {%0,%1,%2,%3}, [%4];"
        : "=r"(r[0]), "=r"(r[1]), "=r"(r[2]), "=r"(r[3]) : "r"(addr));
}

__device__ __forceinline__ uint32_t s2u(const void* p) {
    return (uint32_t)__cvta_generic_to_shared(p);
}
__device__ __forceinline__ void cp16(uint32_t smem_addr, const void* gmem) {
    asm volatile("cp.async.cg.shared.global [%0], [%1], 16;"
                 :: "r"(smem_addr), "l"(gmem));
}
__device__ __forceinline__ void cp_commit() {
    asm volatile("cp.async.commit_group;");
}
template<int N> __device__ __forceinline__ void cp_wait() {
    asm volatile("cp.async.wait_group %0;" :: "n"(N));
}

// ---------------------------------------------------------------------------
// Tensor-core GEMM: D[32 x 64] tile of Qrows[32,KD] @ Crows[64,KD]^T
//   256 threads = 8 warps as 2(m) x 4(n): warp owns 16 rows x 16 cols.
//   4-stage cp.async pipeline, stage = 32 k (12 KB). Raw fp32 in smem,
//   tf32 cvt AFTER ldmatrix (same math as loader-side cvt -> same rel_err).
//   Rows = 32 floats (128B) with 16B-segment XOR swizzle -> LDSM conflict-free.
// LOGITS: Q = g_Qp, adds g_qb, writes logits + rows planes (stride 1024).
// !LOGITS (qp): Q = arg_values, C = W, writes g_Qp (stride 512);
//               blockIdx.x==0 also computes g_qb (quad-shuffle reduction).
// ---------------------------------------------------------------------------
template<int KD, bool LOGITS>
__global__ __launch_bounds__(256, 2) void gemm_tc(const float* __restrict__ Qm,
                                                  const float* __restrict__ Cm,
                                                  const float* __restrict__ bv,
                                                  float* __restrict__ out,
                                                  float* __restrict__ rows_out) {
    constexpr int NST  = KD / 32;                   // total stages of work
    constexpr int S    = 4;                         // pipeline depth
    constexpr int OSTR = LOGITS ? CTX_PER : D_MODEL;

    __shared__ float Qs[S][32 * 32];                // 16 KB
    __shared__ float Cs[S][64 * 32];                // 32 KB

    const int tid  = threadIdx.x;
    const int lane = tid & 31;
    const int warp = tid >> 5;
    const int wm   = warp >> 2;          // 0..1  (row half)
    const int wn   = warp & 3;           // 0..3  (col quarter)
    const int qr   = lane >> 2;
    const int qc   = lane & 3;

    const float* Qbase = LOGITS ? (const float*)g_Qp : Qm;
    const int qrow_base = blockIdx.y * 32;
    const int crow_base = (LOGITS ? blockIdx.y * CTX_PER : 0) + blockIdx.x * 64;
    const int ocol_base = blockIdx.x * 64;

    // ---- loader: 1 Q cp.async + 2 C cp.async per thread per stage
    const int lq_row = tid >> 3;                 // 0..31
    const int lq_seg = tid & 7;                  // 16B segment 0..7
    const float* qsrc = Qbase + (size_t)(qrow_base + lq_row) * KD + lq_seg * 4;
    const int lq_sw  = (lq_seg ^ (lq_row & 7));
    uint32_t qdst[S];
    #pragma unroll
    for (int s = 0; s < S; s++)
        qdst[s] = s2u(&Qs[s][lq_row * 32 + lq_sw * 4]);

    int lc_row[2];
    const float* csrc[2];
    uint32_t cdst[2][S];
    #pragma unroll
    for (int j = 0; j < 2; j++) {
        int id = tid + j * 256;
        lc_row[j] = id >> 3;                     // 0..63
        int seg = id & 7;
        csrc[j] = Cm + (size_t)(crow_base + lc_row[j]) * KD + seg * 4;
        int sw = seg ^ (lc_row[j] & 7);
        #pragma unroll
        for (int s = 0; s < S; s++)
            cdst[j][s] = s2u(&Cs[s][lc_row[j] * 32 + sw * 4]);
    }

    // ---- LDSM lane addressing
    const int arow  = 16 * wm + (lane & 15);
    const int ahi   = lane >> 4;
    const int amask = arow & 7;
    const int brow  = 16 * wn + (lane & 15);
    const int bhi   = lane >> 4;
    const int bmask = brow & 7;
    uint32_t abase[S], bbase[S];
    #pragma unroll
    for (int s = 0; s < S; s++) {
        abase[s] = s2u(&Qs[s][arow * 32]);
        bbase[s] = s2u(&Cs[s][brow * 32]);
    }

    float acc[2][4] = {};                        // [n-tile][frag]

    // ---- prologue: issue stages 0..S-2
    #pragma unroll
    for (int s = 0; s < S - 1; s++) {
        cp16(qdst[s], qsrc + s * 32);
        cp16(cdst[0][s], csrc[0] + s * 32);
        cp16(cdst[1][s], csrc[1] + s * 32);
        cp_commit();
    }

    #pragma unroll 1
    for (int it = 0; it < NST; it++) {
        const int b = it & (S - 1);
        cp_wait<S - 2>();
        __syncthreads();

        // compute stage: 4 k8 steps
        #pragma unroll
        for (int kk = 0; kk < 4; kk++) {
            uint32_t a[4], bt[4];
            const int sa = (kk * 2 + ahi) ^ amask;
            const int sb = (kk * 2 + bhi) ^ bmask;
            ldsm_x4(a, abase[b] + sa * 16);
            ldsm_x4(bt, bbase[b] + sb * 16);
            #pragma unroll
            for (int u = 0; u < 4; u++) { a[u] = bits2tf32(a[u]); bt[u] = bits2tf32(bt[u]); }
            mma_tf32(acc[0], a, bt[0], bt[2]);   // cols 16wn+0..7
            mma_tf32(acc[1], a, bt[1], bt[3]);   // cols 16wn+8..15
        }

        // issue stage it+S-1 into buffer (it-1)%S (safe: barrier above)
        if (it + S - 1 < NST) {
            const int nb = (it + S - 1) & (S - 1);
            const int ks = (it + S - 1) * 32;
            cp16(qdst[nb], qsrc + ks);
            cp16(cdst[0][nb], csrc[0] + ks);
            cp16(cdst[1][nb], csrc[1] + ks);
        }
        cp_commit();                             // unconditional: keeps count
    }

    // ---- epilogue: warp tile rows [16wm,16wm+16), cols [16wn,16wn+16)
    #pragma unroll
    for (int nt = 0; nt < 2; nt++) {
        #pragma unroll
        for (int half = 0; half < 2; half++) {
            const int rg = qrow_base + 16 * wm + qr + half * 8;   // global row
            const int col = ocol_base + 16 * wn + nt * 8 + qc * 2;
            const size_t off = (size_t)rg * OSTR + col;
            float v0 = acc[nt][half * 2 + 0];
            float v1 = acc[nt][half * 2 + 1];
            if (LOGITS) {
                const float qb = g_qb[rg];
                *(float2*)(out + off) = make_float2(v0 + qb, v1 + qb);
                if (rows_out) {
                    float fr = (float)rg;
                    *(float2*)(rows_out + off) = make_float2(fr, fr);
                }
            } else {
                *(float2*)(g_Qp + off) = make_float2(v0, v1);
            }
        }
    }

    // ---- fused qb (qp kernel only, one column of blocks)
    if (!LOGITS && blockIdx.x == 0 && tid < 128) {
        const int row = qrow_base + (tid >> 2);
        const int seg = tid & 3;
        const float* ap = Qm + (size_t)row * KEY_DIM + seg * 32;
        const float* bp = bv + seg * 32;
        float s = 0.f;
        #pragma unroll
        for (int k = 0; k < 8; k++) {
            float4 a  = *(const float4*)(ap + 4 * k);
            float4 bb = *(const float4*)(bp + 4 * k);
            s = fmaf(a.x, bb.x, s); s = fmaf(a.y, bb.y, s);
            s = fmaf(a.z, bb.z, s); s = fmaf(a.w, bb.w, s);
        }
        s += __shfl_xor_sync(0xffffffffu, s, 1);
        s += __shfl_xor_sync(0xffffffffu, s, 2);
        if (seg == 0) g_qb[row] = s;
    }
}

// ---------------------------------------------------------------------------
extern "C" void kernel_launch(void* const* d_in, const int* in_sizes, int n_in,
                              void* d_out, int out_size) {
    // Identify inputs by element count (arg_values and W share 65536 ->
    // disambiguated by order: arg_values precedes W in the input dict).
    const float* argv = nullptr;
    const float* ctxv = nullptr;
    const float* Wm   = nullptr;
    const float* bv   = nullptr;
    int seen_65536 = 0;
    for (int i = 0; i < n_in; i++) {
        long sz = in_sizes[i];
        if (sz == (long)N_CTX * D_MODEL) {
            ctxv = (const float*)d_in[i];
        } else if (sz == (long)N_ARGS * KEY_DIM) {   // == D_MODEL*KEY_DIM too
            if (seen_65536++ == 0) argv = (const float*)d_in[i];
            else                   Wm   = (const float*)d_in[i];
        } else if (sz == KEY_DIM) {
            bv = (const float*)d_in[i];
        }
    }

    float* out        = (float*)d_out;
    float* rows_out   = nullptr;
    float* logits_out = out;
    if (out_size >= 2 * P_TOT) {        // (rows, logits) concatenated
        rows_out   = out;
        logits_out = out + P_TOT;
    }

    // Qp = arg @ W^T (+ fused qb): M=512 rows (16 y-tiles of 32),
    // N=512 dims (8 x-tiles of 64), K=128 (4 pipeline stages of work)
    gemm_tc<KEY_DIM, false><<<dim3(8, 16), 256>>>(argv, Wm, bv, nullptr, nullptr);

    // logits: per state (blockIdx.y): [32,1024] = Qp_s @ C_s^T + qb,
    // 16 x-tiles of 64 cols, K=512 (16 stages) -> 256 CTAs, 2 CTAs/SM
    gemm_tc<D_MODEL, true><<<dim3(16, 16), 256>>>(nullptr, ctxv, nullptr,
                                                  logits_out, rows_out);
}

// round 10
// speedup vs baseline: 1.3845x; 1.1345x over previous
#include <cuda_runtime.h>
#include <cstdint>

#define D_MODEL 512
#define KEY_DIM 128
#define BS_N 16
#define CTX_PER 1024
#define ARGS_PER 32
#define N_ARGS (BS_N * ARGS_PER)      /* 512  */
#define N_CTX  (BS_N * CTX_PER)       /* 16384 */
#define P_TOT  (N_ARGS * CTX_PER)     /* 524288 */

// Scratch (allocation-free rule: device globals). Accessed ONLY from device
// code -- host-side references give the host shadow symbol (R3 bug).
// g_Qp holds TF32-ROUNDED values (rounded in qp epilogue) so the logits
// kernel can feed A fragments to mma.tf32 without any cvt.
__device__ float g_Qp[N_ARGS * D_MODEL];
__device__ float g_qb[N_ARGS];

// ---------------------------------------------------------------------------
__device__ __forceinline__ uint32_t f2tf32(float f) {
    uint32_t r;
    asm("cvt.rna.tf32.f32 %0, %1;" : "=r"(r) : "f"(f));
    return r;
}
__device__ __forceinline__ uint32_t bits2tf32(uint32_t b) {
    return f2tf32(__uint_as_float(b));
}

// D(16x8) += A(16x8,row) * B(8x8,col)   tf32 inputs, fp32 accum
__device__ __forceinline__ void mma_tf32(float (&d)[4], const uint32_t (&a)[4],
                                         uint32_t b0, uint32_t b1) {
    asm volatile(
        "mma.sync.aligned.m16n8k8.row.col.f32.tf32.tf32.f32 "
        "{%0,%1,%2,%3}, {%4,%5,%6,%7}, {%8,%9}, {%0,%1,%2,%3};"
        : "+f"(d[0]), "+f"(d[1]), "+f"(d[2]), "+f"(d[3])
        : "r"(a[0]), "r"(a[1]), "r"(a[2]), "r"(a[3]), "r"(b0), "r"(b1));
}

// ldmatrix x4 (b16 view of 32-bit data): verified on HW in R7/R8/R9.
__device__ __forceinline__ void ldsm_x4(uint32_t (&r)[4], uint32_t addr) {
    asm volatile(
        "ldmatrix.sync.aligned.m8n8.x4.shared.b16 {%0,%1,%2,%3}, [%4];"
        : "=r"(r[0]), "=r"(r[1]), "=r"(r[2]), "=r"(r[3]) : "r"(addr));
}

__device__ __forceinline__ uint32_t s2u(const void* p) {
    return (uint32_t)__cvta_generic_to_shared(p);
}
__device__ __forceinline__ void cp16(uint32_t smem_addr, const void* gmem) {
    asm volatile("cp.async.cg.shared.global [%0], [%1], 16;"
                 :: "r"(smem_addr), "l"(gmem));
}
__device__ __forceinline__ void cp_commit() {
    asm volatile("cp.async.commit_group;");
}
template<int N> __device__ __forceinline__ void cp_wait() {
    asm volatile("cp.async.wait_group %0;" :: "n"(N));
}

// ---------------------------------------------------------------------------
// Tensor-core GEMM: D[32 x 64] tile of Qrows[32,KD] @ Crows[64,KD]^T
//   256 threads = 8 warps as 2(m) x 4(n). 4-stage cp.async pipeline,
//   stage = 32 k. Main loop unrolled x4 so the stage slot is compile-time ->
//   every smem address is reg+immediate (no dynamic-indexed arrays, the R9
//   local-memory trap). XOR-swizzled 128B rows -> conflict-free LDSM.
// LOGITS: A (g_Qp) is pre-rounded tf32 -> NO cvt on A; C gets 4 cvts/kk.
// !LOGITS (qp): cvts both operands; epilogue stores tf32-rounded g_Qp;
//               blockIdx.x==0 also computes g_qb.
// ---------------------------------------------------------------------------
template<int KD, bool LOGITS>
__global__ __launch_bounds__(256, 2) void gemm_tc(const float* __restrict__ Qm,
                                                  const float* __restrict__ Cm,
                                                  const float* __restrict__ bv,
                                                  float* __restrict__ out,
                                                  float* __restrict__ rows_out) {
    constexpr int NST  = KD / 32;                   // total k-stages of work
    constexpr int S    = 4;                         // pipeline depth
    constexpr int OSTR = LOGITS ? CTX_PER : D_MODEL;
    constexpr uint32_t QSTG = 32 * 32 * 4;          // 4 KB per Q stage
    constexpr uint32_t CSTG = 64 * 32 * 4;          // 8 KB per C stage

    __shared__ float Qs[S * 32 * 32];               // 16 KB
    __shared__ float Cs[S * 64 * 32];               // 32 KB

    const int tid  = threadIdx.x;
    const int lane = tid & 31;
    const int warp = tid >> 5;
    const int wm   = warp >> 2;
    const int wn   = warp & 3;
    const int qr   = lane >> 2;
    const int qc   = lane & 3;

    const float* Qbase = LOGITS ? (const float*)g_Qp : Qm;
    const int qrow_base = blockIdx.y * 32;
    const int crow_base = (LOGITS ? blockIdx.y * CTX_PER : 0) + blockIdx.x * 64;
    const int ocol_base = blockIdx.x * 64;

    const uint32_t QsU = s2u(Qs);
    const uint32_t CsU = s2u(Cs);

    // ---- loader offsets (bytes within a stage)
    const int lq_row = tid >> 3;
    const int lq_seg = tid & 7;
    const float* qsrc = Qbase + (size_t)(qrow_base + lq_row) * KD + lq_seg * 4;
    const uint32_t qoff = (uint32_t)(lq_row * 32 + (lq_seg ^ (lq_row & 7)) * 4) * 4;

    const int lc_row0 = tid >> 3;                   // 0..31
    const int lc_row1 = lc_row0 + 32;               // 32..63
    const float* csrc0 = Cm + (size_t)(crow_base + lc_row0) * KD + lq_seg * 4;
    const float* csrc1 = Cm + (size_t)(crow_base + lc_row1) * KD + lq_seg * 4;
    const uint32_t coff0 = (uint32_t)(lc_row0 * 32 + (lq_seg ^ (lc_row0 & 7)) * 4) * 4;
    const uint32_t coff1 = (uint32_t)(lc_row1 * 32 + (lq_seg ^ (lc_row1 & 7)) * 4) * 4;

    // ---- LDSM per-kk byte offsets (compile-time-unrolled kk, constant regs)
    const int arow  = 16 * wm + (lane & 15);
    const int ahi   = lane >> 4;
    const int amask = arow & 7;
    const int brow  = 16 * wn + (lane & 15);
    const int bmask = brow & 7;
    uint32_t aoff[4], boff[4];
    #pragma unroll
    for (int kk = 0; kk < 4; kk++) {
        aoff[kk] = (uint32_t)(arow * 128 + (((kk * 2 + ahi) ^ amask) * 16));
        boff[kk] = (uint32_t)(brow * 128 + (((kk * 2 + ahi) ^ bmask) * 16));
    }

    float acc[2][4] = {};

    // ---- prologue: issue stages 0..S-2 (slots are literals)
    #pragma unroll
    for (int s = 0; s < S - 1; s++) {
        cp16(QsU + s * QSTG + qoff, qsrc + s * 32);
        cp16(CsU + s * CSTG + coff0, csrc0 + s * 32);
        cp16(CsU + s * CSTG + coff1, csrc1 + s * 32);
        cp_commit();
    }

    // ---- main loop: x4 inner unroll makes stage slot compile-time
    #pragma unroll 1
    for (int it4 = 0; it4 < NST / 4; it4++) {
        #pragma unroll
        for (int s = 0; s < 4; s++) {
            const int st = it4 * 4 + s;
            cp_wait<S - 2>();
            __syncthreads();

            const uint32_t qstage = QsU + s * QSTG;   // immediate offset
            const uint32_t cstage = CsU + s * CSTG;
            #pragma unroll
            for (int kk = 0; kk < 4; kk++) {
                uint32_t a[4], bt[4];
                ldsm_x4(a, qstage + aoff[kk]);
                ldsm_x4(bt, cstage + boff[kk]);
                if (!LOGITS) {                        // qp: raw inputs need cvt
                    #pragma unroll
                    for (int u = 0; u < 4; u++) a[u] = bits2tf32(a[u]);
                }
                #pragma unroll
                for (int u = 0; u < 4; u++) bt[u] = bits2tf32(bt[u]);
                mma_tf32(acc[0], a, bt[0], bt[2]);
                mma_tf32(acc[1], a, bt[1], bt[3]);
            }

            if (st + S - 1 < NST) {
                const int nb = (s + S - 1) & (S - 1); // compile-time slot
                const int ks = (st + S - 1) * 32;
                cp16(QsU + nb * QSTG + qoff, qsrc + ks);
                cp16(CsU + nb * CSTG + coff0, csrc0 + ks);
                cp16(CsU + nb * CSTG + coff1, csrc1 + ks);
            }
            cp_commit();
        }
    }

    // ---- epilogue: warp tile rows [16wm,16wm+16), cols [16wn,16wn+16)
    #pragma unroll
    for (int nt = 0; nt < 2; nt++) {
        #pragma unroll
        for (int half = 0; half < 2; half++) {
            const int rg = qrow_base + 16 * wm + qr + half * 8;
            const int col = ocol_base + 16 * wn + nt * 8 + qc * 2;
            const size_t off = (size_t)rg * OSTR + col;
            float v0 = acc[nt][half * 2 + 0];
            float v1 = acc[nt][half * 2 + 1];
            if (LOGITS) {
                const float qb = g_qb[rg];
                *(float2*)(out + off) = make_float2(v0 + qb, v1 + qb);
                if (rows_out) {
                    float fr = (float)rg;
                    *(float2*)(rows_out + off) = make_float2(fr, fr);
                }
            } else {
                // store TF32-ROUNDED so logits kernel needs no cvt on A
                *(float2*)(g_Qp + off) =
                    make_float2(__uint_as_float(f2tf32(v0)),
                                __uint_as_float(f2tf32(v1)));
            }
        }
    }

    // ---- fused qb (qp kernel only, one column of blocks)
    if (!LOGITS && blockIdx.x == 0 && tid < 128) {
        const int row = qrow_base + (tid >> 2);
        const int seg = tid & 3;
        const float* ap = Qm + (size_t)row * KEY_DIM + seg * 32;
        const float* bp = bv + seg * 32;
        float s = 0.f;
        #pragma unroll
        for (int k = 0; k < 8; k++) {
            float4 a  = *(const float4*)(ap + 4 * k);
            float4 bb = *(const float4*)(bp + 4 * k);
            s = fmaf(a.x, bb.x, s); s = fmaf(a.y, bb.y, s);
            s = fmaf(a.z, bb.z, s); s = fmaf(a.w, bb.w, s);
        }
        s += __shfl_xor_sync(0xffffffffu, s, 1);
        s += __shfl_xor_sync(0xffffffffu, s, 2);
        if (seg == 0) g_qb[row] = s;
    }
}

// ---------------------------------------------------------------------------
extern "C" void kernel_launch(void* const* d_in, const int* in_sizes, int n_in,
                              void* d_out, int out_size) {
    const float* argv = nullptr;
    const float* ctxv = nullptr;
    const float* Wm   = nullptr;
    const float* bv   = nullptr;
    int seen_65536 = 0;
    for (int i = 0; i < n_in; i++) {
        long sz = in_sizes[i];
        if (sz == (long)N_CTX * D_MODEL) {
            ctxv = (const float*)d_in[i];
        } else if (sz == (long)N_ARGS * KEY_DIM) {   // == D_MODEL*KEY_DIM too
            if (seen_65536++ == 0) argv = (const float*)d_in[i];
            else                   Wm   = (const float*)d_in[i];
        } else if (sz == KEY_DIM) {
            bv = (const float*)d_in[i];
        }
    }

    float* out        = (float*)d_out;
    float* rows_out   = nullptr;
    float* logits_out = out;
    if (out_size >= 2 * P_TOT) {        // (rows, logits) concatenated
        rows_out   = out;
        logits_out = out + P_TOT;
    }

    // Qp = arg @ W^T (+ fused qb), output tf32-rounded: K=128 (4 stages)
    gemm_tc<KEY_DIM, false><<<dim3(8, 16), 256>>>(argv, Wm, bv, nullptr, nullptr);

    // logits: per state: [32,1024] = Qp_s @ C_s^T + qb, K=512 (16 stages)
    gemm_tc<D_MODEL, true><<<dim3(16, 16), 256>>>(nullptr, ctxv, nullptr,
                                                  logits_out, rows_out);
}